// round 2
// baseline (speedup 1.0000x reference)
#include <cuda_runtime.h>
#include <math.h>

// Problem constants
#define BB   2
#define LL   2048
#define DM   1024
#define HH   16
#define DKK  64
#define MROWS (BB*LL)          // 4096
#define INV_SCALE 0.125f       // 1/sqrt(64)

// Scratch (allocation-free: __device__ globals, 64 MB bss total)
__device__ float g_q[(size_t)BB*HH*LL*DKK];
__device__ float g_k[(size_t)BB*HH*LL*DKK];
__device__ float g_v[(size_t)BB*HH*LL*DKK];
__device__ float g_ctx[(size_t)BB*LL*DM];

// ---------------------------------------------------------------------------
// NT sgemm: C[m][n] = sum_k A[m][k] * W[n][k]
// A: (MROWS, DM) row-major, W: (DM, DM) row-major. BM=BN=128, BK=8, 8x8 micro.
// mode 0: C row-major (MROWS, DM)
// mode 1: C in head layout: C[((b*H + n/64)*L + l)*64 + n%64]
// ---------------------------------------------------------------------------
__global__ __launch_bounds__(256) void gemm_nt_kernel(
    const float* __restrict__ A, const float* __restrict__ W,
    float* __restrict__ C, int mode)
{
    __shared__ float As[8][128];
    __shared__ float Ws[8][128];
    const int K = DM;
    const int tid = threadIdx.x;
    const int tx = tid & 15, ty = tid >> 4;
    const int m0 = blockIdx.y * 128;
    const int n0 = blockIdx.x * 128;

    float acc[8][8];
    #pragma unroll
    for (int i = 0; i < 8; i++)
        #pragma unroll
        for (int j = 0; j < 8; j++) acc[i][j] = 0.f;

    const int lrow = tid >> 1;
    const int lcol = (tid & 1) * 4;
    const float* Ap = A + (size_t)(m0 + lrow) * K + lcol;
    const float* Wp = W + (size_t)(n0 + lrow) * K + lcol;

    for (int k0 = 0; k0 < K; k0 += 8) {
        float4 av = *(const float4*)(Ap + k0);
        float4 wv = *(const float4*)(Wp + k0);
        As[lcol+0][lrow] = av.x; As[lcol+1][lrow] = av.y;
        As[lcol+2][lrow] = av.z; As[lcol+3][lrow] = av.w;
        Ws[lcol+0][lrow] = wv.x; Ws[lcol+1][lrow] = wv.y;
        Ws[lcol+2][lrow] = wv.z; Ws[lcol+3][lrow] = wv.w;
        __syncthreads();
        #pragma unroll
        for (int kk = 0; kk < 8; kk++) {
            float a[8], b[8];
            #pragma unroll
            for (int i = 0; i < 8; i++) a[i] = As[kk][ty*8 + i];
            #pragma unroll
            for (int j = 0; j < 8; j++) b[j] = Ws[kk][tx*8 + j];
            #pragma unroll
            for (int i = 0; i < 8; i++)
                #pragma unroll
                for (int j = 0; j < 8; j++)
                    acc[i][j] = fmaf(a[i], b[j], acc[i][j]);
        }
        __syncthreads();
    }

    if (mode == 0) {
        #pragma unroll
        for (int i = 0; i < 8; i++) {
            const int m = m0 + ty*8 + i;
            float* Cp = C + (size_t)m * DM + n0 + tx*8;
            *(float4*)(Cp)     = make_float4(acc[i][0], acc[i][1], acc[i][2], acc[i][3]);
            *(float4*)(Cp + 4) = make_float4(acc[i][4], acc[i][5], acc[i][6], acc[i][7]);
        }
    } else {
        const int n = n0 + tx*8;         // 8 cols always inside one 64-wide head
        const int h = n / DKK, d = n % DKK;
        #pragma unroll
        for (int i = 0; i < 8; i++) {
            const int m  = m0 + ty*8 + i;
            const int b_ = m / LL, l = m % LL;
            float* Cp = C + (((size_t)(b_*HH + h) * LL + l) * DKK + d);
            *(float4*)(Cp)     = make_float4(acc[i][0], acc[i][1], acc[i][2], acc[i][3]);
            *(float4*)(Cp + 4) = make_float4(acc[i][4], acc[i][5], acc[i][6], acc[i][7]);
        }
    }
}

// ---------------------------------------------------------------------------
// Flash attention with additive bias + mask, fp32, online softmax.
// Grid: (L/128, B*H). Block 256 threads (tx 0..15, ty 0..15).
// Q tile 128x64 in smem; per key-tile (64 keys): K,V tiles in smem,
// S in regs (rows ty+16i, cols tx+16j), P staged via smem for the PV gemm.
// smem stride 65 -> conflict-free strided reads.
// ---------------------------------------------------------------------------
#define ATT_SMEM_FLOATS ((128 + 64 + 64 + 128) * 65)

__global__ __launch_bounds__(256) void attn_kernel(
    const float* __restrict__ Q, const float* __restrict__ K,
    const float* __restrict__ V, const float* __restrict__ bias,
    const float* __restrict__ mask, float* __restrict__ ctx)
{
    extern __shared__ float sm[];
    float* q_s = sm;                  // 128 x 65
    float* k_s = q_s + 128 * 65;      // 64 x 65
    float* v_s = k_s + 64 * 65;       // 64 x 65
    float* p_s = v_s + 64 * 65;       // 128 x 65

    const int tid = threadIdx.x;
    const int tx = tid & 15, ty = tid >> 4;
    const int bh = blockIdx.y;
    const int b  = bh / HH;
    const int h  = bh % HH;
    const int q0 = blockIdx.x * 128;

    const float* Qb = Q + (size_t)bh * LL * DKK;
    const float* Kb = K + (size_t)bh * LL * DKK;
    const float* Vb = V + (size_t)bh * LL * DKK;
    const float* biasb = bias + (size_t)bh * LL * LL;
    const float* maskb = mask + (size_t)b * LL;

    // Load Q tile: 128x64 floats = 2048 float4s
    for (int i = tid; i < 128 * 16; i += 256) {
        const int r = i >> 4;
        const int c = (i & 15) * 4;
        float4 v4 = *(const float4*)&Qb[(size_t)(q0 + r) * DKK + c];
        q_s[r*65 + c + 0] = v4.x; q_s[r*65 + c + 1] = v4.y;
        q_s[r*65 + c + 2] = v4.z; q_s[r*65 + c + 3] = v4.w;
    }

    float m_i[8], l_i[8], o[8][4];
    #pragma unroll
    for (int i = 0; i < 8; i++) {
        m_i[i] = -INFINITY; l_i[i] = 0.f;
        #pragma unroll
        for (int j = 0; j < 4; j++) o[i][j] = 0.f;
    }

    for (int kt = 0; kt < LL / 64; kt++) {
        const int k0 = kt * 64;
        __syncthreads();   // protects k/v/p from previous iteration; first iter: Q tile
        // Load K, V tiles (64x64 each)
        for (int i = tid; i < 64 * 16; i += 256) {
            const int r = i >> 4;
            const int c = (i & 15) * 4;
            float4 kv = *(const float4*)&Kb[(size_t)(k0 + r) * DKK + c];
            float4 vv = *(const float4*)&Vb[(size_t)(k0 + r) * DKK + c];
            k_s[r*65 + c + 0] = kv.x; k_s[r*65 + c + 1] = kv.y;
            k_s[r*65 + c + 2] = kv.z; k_s[r*65 + c + 3] = kv.w;
            v_s[r*65 + c + 0] = vv.x; v_s[r*65 + c + 1] = vv.y;
            v_s[r*65 + c + 2] = vv.z; v_s[r*65 + c + 3] = vv.w;
        }
        __syncthreads();

        // S = Q K^T  (rows ty+16i, cols tx+16j)
        float s[8][4];
        #pragma unroll
        for (int i = 0; i < 8; i++)
            #pragma unroll
            for (int j = 0; j < 4; j++) s[i][j] = 0.f;

        #pragma unroll 4
        for (int d = 0; d < 64; d++) {
            float a[8], bb[4];
            #pragma unroll
            for (int i = 0; i < 8; i++) a[i] = q_s[(ty + 16*i)*65 + d];
            #pragma unroll
            for (int j = 0; j < 4; j++) bb[j] = k_s[(tx + 16*j)*65 + d];
            #pragma unroll
            for (int i = 0; i < 8; i++)
                #pragma unroll
                for (int j = 0; j < 4; j++)
                    s[i][j] = fmaf(a[i], bb[j], s[i][j]);
        }

        // scale + bias + mask, online softmax
        #pragma unroll
        for (int i = 0; i < 8; i++) {
            const int qr = q0 + ty + 16*i;
            const float* brow = biasb + (size_t)qr * LL + k0;
            float mx = -INFINITY;
            #pragma unroll
            for (int j = 0; j < 4; j++) {
                const int kc = tx + 16*j;
                s[i][j] = fmaf(s[i][j], INV_SCALE, brow[kc] + maskb[k0 + kc]);
                mx = fmaxf(mx, s[i][j]);
            }
            #pragma unroll
            for (int off = 8; off > 0; off >>= 1)
                mx = fmaxf(mx, __shfl_xor_sync(0xffffffffu, mx, off));
            const float mnew = fmaxf(m_i[i], mx);
            const float corr = __expf(m_i[i] - mnew);
            m_i[i] = mnew;
            float rs = 0.f;
            #pragma unroll
            for (int j = 0; j < 4; j++) {
                s[i][j] = __expf(s[i][j] - mnew);
                rs += s[i][j];
            }
            #pragma unroll
            for (int off = 8; off > 0; off >>= 1)
                rs += __shfl_xor_sync(0xffffffffu, rs, off);
            l_i[i] = l_i[i] * corr + rs;
            #pragma unroll
            for (int j = 0; j < 4; j++) o[i][j] *= corr;
            #pragma unroll
            for (int j = 0; j < 4; j++)
                p_s[(ty + 16*i)*65 + tx + 16*j] = s[i][j];
        }
        __syncthreads();

        // O += P V  (rows ty+16i, d-cols tx+16j)
        #pragma unroll 4
        for (int kc = 0; kc < 64; kc++) {
            float a[8], bb[4];
            #pragma unroll
            for (int i = 0; i < 8; i++) a[i] = p_s[(ty + 16*i)*65 + kc];
            #pragma unroll
            for (int j = 0; j < 4; j++) bb[j] = v_s[kc*65 + tx + 16*j];
            #pragma unroll
            for (int i = 0; i < 8; i++)
                #pragma unroll
                for (int j = 0; j < 4; j++)
                    o[i][j] = fmaf(a[i], bb[j], o[i][j]);
        }
    }

    // Epilogue: ctx in (B, L, H*DK) layout for the output projection
    #pragma unroll
    for (int i = 0; i < 8; i++) {
        const int qr = q0 + ty + 16*i;
        const float inv_l = 1.0f / l_i[i];
        #pragma unroll
        for (int j = 0; j < 4; j++) {
            const int dc = tx + 16*j;
            ctx[((size_t)(b*LL + qr)) * DM + h*DKK + dc] = o[i][j] * inv_l;
        }
    }
}

// ---------------------------------------------------------------------------
extern "C" void kernel_launch(void* const* d_in, const int* in_sizes, int n_in,
                              void* d_out, int out_size)
{
    const float* x    = (const float*)d_in[0];
    const float* Wq   = (const float*)d_in[1];
    const float* Wk   = (const float*)d_in[2];
    const float* Wv   = (const float*)d_in[3];
    const float* Wo   = (const float*)d_in[4];
    const float* bias = (const float*)d_in[5];
    const float* mask = (const float*)d_in[6];
    float* out = (float*)d_out;

    float *qp, *kp, *vp, *cp;
    cudaGetSymbolAddress((void**)&qp, g_q);
    cudaGetSymbolAddress((void**)&kp, g_k);
    cudaGetSymbolAddress((void**)&vp, g_v);
    cudaGetSymbolAddress((void**)&cp, g_ctx);

    const dim3 ggrid(DM / 128, MROWS / 128);   // (8, 32)
    gemm_nt_kernel<<<ggrid, 256>>>(x, Wq, qp, 1);
    gemm_nt_kernel<<<ggrid, 256>>>(x, Wk, kp, 1);
    gemm_nt_kernel<<<ggrid, 256>>>(x, Wv, vp, 1);

    const int smem_bytes = ATT_SMEM_FLOATS * (int)sizeof(float);  // 99840
    cudaFuncSetAttribute(attn_kernel,
                         cudaFuncAttributeMaxDynamicSharedMemorySize, smem_bytes);
    attn_kernel<<<dim3(LL / 128, BB * HH), 256, smem_bytes>>>(qp, kp, vp, bias, mask, cp);

    gemm_nt_kernel<<<ggrid, 256>>>(cp, Wo, out, 0);
}

// round 4
// speedup vs baseline: 1.1937x; 1.1937x over previous
#include <cuda_runtime.h>
#include <math.h>

// Problem constants
#define BB   2
#define LL   2048
#define DM   1024
#define HH   16
#define DKK  64
#define MROWS (BB*LL)          // 4096
#define INV_SCALE 0.125f       // 1/sqrt(64)

typedef unsigned long long ull;

// Scratch (allocation-free: __device__ globals)
__device__ float g_q[(size_t)BB*HH*LL*DKK];
__device__ float g_k[(size_t)BB*HH*LL*DKK];
__device__ float g_v[(size_t)BB*HH*LL*DKK];
__device__ float g_ctx[(size_t)BB*LL*DM];

// ---------------- packed f32x2 helpers (sm_100+) ----------------
__device__ __forceinline__ void ffma2(ull &d, ull a, ull b) {
    asm("fma.rn.f32x2 %0, %1, %2, %0;" : "+l"(d) : "l"(a), "l"(b));
}
__device__ __forceinline__ void fmul2(ull &d, ull a) {
    asm("mul.rn.f32x2 %0, %0, %1;" : "+l"(d) : "l"(a));
}
__device__ __forceinline__ ull pack2(float x, float y) {
    ull r; asm("mov.b64 %0, {%1, %2};" : "=l"(r) : "f"(x), "f"(y)); return r;
}
__device__ __forceinline__ void unpack2(ull v, float &x, float &y) {
    asm("mov.b64 {%0, %1}, %2;" : "=f"(x), "=f"(y) : "l"(v));
}

// ---------------------------------------------------------------------------
// NT sgemm: C[m][n] = sum_k A[m][k] * W[n][k]   (f32x2 packed math)
// A: (MROWS, DM), W: (DM, DM) row-major. BM=BN=128, BK=8, 256 threads.
// Fragments: rows {ty*4..+3, 64+ty*4..+3}, cols {tx*4..+3, 64+tx*4..+3}.
// Smem k-major with stride 132 -> conflict-free LDS.128 + STS.
// mode 0: C row-major; mode 1: head layout C[((b*H + n/64)*L + l)*64 + n%64]
// ---------------------------------------------------------------------------
__global__ __launch_bounds__(256) void gemm_nt_kernel(
    const float* __restrict__ A, const float* __restrict__ W,
    float* __restrict__ C, int mode)
{
    __shared__ float As[8][132];
    __shared__ float Ws[8][132];
    const int K = DM;
    const int tid = threadIdx.x;
    const int tx = tid & 15, ty = tid >> 4;
    const int m0 = blockIdx.y * 128;
    const int n0 = blockIdx.x * 128;

    ull acc[8][4];
    #pragma unroll
    for (int i = 0; i < 8; i++)
        #pragma unroll
        for (int j = 0; j < 4; j++) acc[i][j] = 0ull;

    const int lrow = tid >> 1;
    const int lcol = (tid & 1) * 4;
    const float* Ap = A + (size_t)(m0 + lrow) * K + lcol;
    const float* Wp = W + (size_t)(n0 + lrow) * K + lcol;

    for (int k0 = 0; k0 < K; k0 += 8) {
        float4 av = *(const float4*)(Ap + k0);
        float4 wv = *(const float4*)(Wp + k0);
        __syncthreads();
        As[lcol+0][lrow] = av.x; As[lcol+1][lrow] = av.y;
        As[lcol+2][lrow] = av.z; As[lcol+3][lrow] = av.w;
        Ws[lcol+0][lrow] = wv.x; Ws[lcol+1][lrow] = wv.y;
        Ws[lcol+2][lrow] = wv.z; Ws[lcol+3][lrow] = wv.w;
        __syncthreads();
        #pragma unroll
        for (int kk = 0; kk < 8; kk++) {
            float4 a0 = *(const float4*)&As[kk][ty*4];
            float4 a1 = *(const float4*)&As[kk][64 + ty*4];
            float4 b0 = *(const float4*)&Ws[kk][tx*4];
            float4 b1 = *(const float4*)&Ws[kk][64 + tx*4];
            ull bp[4] = { pack2(b0.x,b0.y), pack2(b0.z,b0.w),
                          pack2(b1.x,b1.y), pack2(b1.z,b1.w) };
            float ar[8] = { a0.x,a0.y,a0.z,a0.w, a1.x,a1.y,a1.z,a1.w };
            #pragma unroll
            for (int i = 0; i < 8; i++) {
                ull aa = pack2(ar[i], ar[i]);
                #pragma unroll
                for (int j = 0; j < 4; j++) ffma2(acc[i][j], aa, bp[j]);
            }
        }
    }

    #pragma unroll
    for (int i = 0; i < 8; i++) {
        const int m = m0 + ((i < 4) ? (ty*4 + i) : (64 + ty*4 + i - 4));
        #pragma unroll
        for (int g = 0; g < 2; g++) {
            float c0, c1, c2, c3;
            unpack2(acc[i][g*2+0], c0, c1);
            unpack2(acc[i][g*2+1], c2, c3);
            float4 v4 = make_float4(c0, c1, c2, c3);
            const int n = n0 + g*64 + tx*4;
            if (mode == 0) {
                *(float4*)(C + (size_t)m * DM + n) = v4;
            } else {
                const int h = n / DKK, d = n % DKK;
                const int b_ = m / LL, l = m % LL;
                *(float4*)(C + (((size_t)(b_*HH + h) * LL + l) * DKK + d)) = v4;
            }
        }
    }
}

// ---------------------------------------------------------------------------
// Flash attention, fp32 packed f32x2, online softmax, bias + mask.
// Grid: (L/128, B*H). Block 256. q-tile 128 x k-tile 64.
// qT[d][row] (stride 132), kT[d][col] (stride 68): all compute reads are
// LDS.128 broadcast or 16-consecutive (conflict-free). Q pre-scaled by 1/8.
// ---------------------------------------------------------------------------
#define QT_S 132
#define KT_S 68
#define VS_S 68
#define PS_S 68
#define ATT_SMEM_FLOATS (64*QT_S + 64*KT_S + 64*VS_S + 128*PS_S)  // 25856

__global__ __launch_bounds__(256, 2) void attn_kernel(
    const float* __restrict__ Q, const float* __restrict__ K,
    const float* __restrict__ V, const float* __restrict__ bias,
    const float* __restrict__ mask, float* __restrict__ ctx)
{
    extern __shared__ float sm[];
    float* qT  = sm;                    // [64][132] d-major
    float* kT  = qT + 64*QT_S;          // [64][68]  d-major
    float* v_s = kT + 64*KT_S;          // [64][68]  kc-major
    float* p_s = v_s + 64*VS_S;         // [128][68] row-major

    const int tid = threadIdx.x;
    const int tx = tid & 15, ty = tid >> 4;
    const int bh = blockIdx.y;
    const int b  = bh / HH;
    const int h  = bh % HH;
    const int q0 = blockIdx.x * 128;

    const float* Qb = Q + (size_t)bh * LL * DKK;
    const float* Kb = K + (size_t)bh * LL * DKK;
    const float* Vb = V + (size_t)bh * LL * DKK;
    const float* biasb = bias + (size_t)bh * LL * LL;
    const float* maskb = mask + (size_t)b * LL;

    int row[8];
    #pragma unroll
    for (int i = 0; i < 8; i++)
        row[i] = (i < 4) ? (ty*4 + i) : (64 + ty*4 + i - 4);

    // Load Q tile transposed, pre-scaled by 1/sqrt(dk)
    for (int i = tid; i < 128 * 16; i += 256) {
        const int r = i >> 4;
        const int c = (i & 15) * 4;
        float4 v4 = *(const float4*)&Qb[(size_t)(q0 + r) * DKK + c];
        qT[(c+0)*QT_S + r] = v4.x * INV_SCALE;
        qT[(c+1)*QT_S + r] = v4.y * INV_SCALE;
        qT[(c+2)*QT_S + r] = v4.z * INV_SCALE;
        qT[(c+3)*QT_S + r] = v4.w * INV_SCALE;
    }

    float m_i[8], l_i[8];
    ull o2[8][2];
    #pragma unroll
    for (int i = 0; i < 8; i++) {
        m_i[i] = -INFINITY; l_i[i] = 0.f;
        o2[i][0] = 0ull; o2[i][1] = 0ull;
    }

    for (int kt = 0; kt < LL / 64; kt++) {
        const int k0 = kt * 64;
        __syncthreads();   // prev PV done (v_s/p_s); first iter: Q stores done
        for (int i = tid; i < 64 * 16; i += 256) {
            const int r = i >> 4;
            const int c = (i & 15) * 4;
            float4 kv = *(const float4*)&Kb[(size_t)(k0 + r) * DKK + c];
            kT[(c+0)*KT_S + r] = kv.x; kT[(c+1)*KT_S + r] = kv.y;
            kT[(c+2)*KT_S + r] = kv.z; kT[(c+3)*KT_S + r] = kv.w;
            float4 vv = *(const float4*)&Vb[(size_t)(k0 + r) * DKK + c];
            *(float4*)&v_s[r*VS_S + c] = vv;
        }
        __syncthreads();

        // ---- S = Q K^T (packed over col pairs) ----
        ull s2[8][2];
        #pragma unroll
        for (int i = 0; i < 8; i++) { s2[i][0] = 0ull; s2[i][1] = 0ull; }

        #pragma unroll 4
        for (int d = 0; d < 64; d++) {
            float4 a0 = *(const float4*)&qT[d*QT_S + ty*4];
            float4 a1 = *(const float4*)&qT[d*QT_S + 64 + ty*4];
            float4 bv = *(const float4*)&kT[d*KT_S + tx*4];
            ull bp0 = pack2(bv.x, bv.y);
            ull bp1 = pack2(bv.z, bv.w);
            float ar[8] = { a0.x,a0.y,a0.z,a0.w, a1.x,a1.y,a1.z,a1.w };
            #pragma unroll
            for (int i = 0; i < 8; i++) {
                ull aa = pack2(ar[i], ar[i]);
                ffma2(s2[i][0], aa, bp0);
                ffma2(s2[i][1], aa, bp1);
            }
        }

        // ---- softmax (bias + mask), write P ----
        float4 mk = *(const float4*)&maskb[k0 + tx*4];
        #pragma unroll
        for (int i = 0; i < 8; i++) {
            float4 bsv = *(const float4*)&biasb[(size_t)(q0 + row[i]) * LL + k0 + tx*4];
            float s0, s1, sv2, s3;
            unpack2(s2[i][0], s0, s1);
            unpack2(s2[i][1], sv2, s3);
            s0 += bsv.x + mk.x; s1 += bsv.y + mk.y;
            sv2 += bsv.z + mk.z; s3 += bsv.w + mk.w;
            float mx = fmaxf(fmaxf(s0, s1), fmaxf(sv2, s3));
            #pragma unroll
            for (int off = 8; off > 0; off >>= 1)
                mx = fmaxf(mx, __shfl_xor_sync(0xffffffffu, mx, off));
            const float mnew = fmaxf(m_i[i], mx);
            const float corr = __expf(m_i[i] - mnew);
            m_i[i] = mnew;
            float p0 = __expf(s0 - mnew), p1 = __expf(s1 - mnew);
            float p2 = __expf(sv2 - mnew), p3 = __expf(s3 - mnew);
            float rs = (p0 + p1) + (p2 + p3);
            #pragma unroll
            for (int off = 8; off > 0; off >>= 1)
                rs += __shfl_xor_sync(0xffffffffu, rs, off);
            l_i[i] = l_i[i] * corr + rs;
            ull cc = pack2(corr, corr);
            fmul2(o2[i][0], cc);
            fmul2(o2[i][1], cc);
            *(float4*)&p_s[row[i]*PS_S + tx*4] = make_float4(p0, p1, p2, p3);
        }
        __syncthreads();

        // ---- O += P V (packed over d-col pairs) ----
        #pragma unroll 2
        for (int kc0 = 0; kc0 < 64; kc0 += 4) {
            float ap[8][4];
            #pragma unroll
            for (int i = 0; i < 8; i++)
                *(float4*)ap[i] = *(const float4*)&p_s[row[i]*PS_S + kc0];
            #pragma unroll
            for (int t = 0; t < 4; t++) {
                float4 bv = *(const float4*)&v_s[(kc0 + t)*VS_S + tx*4];
                ull bp0 = pack2(bv.x, bv.y);
                ull bp1 = pack2(bv.z, bv.w);
                #pragma unroll
                for (int i = 0; i < 8; i++) {
                    ull aa = pack2(ap[i][t], ap[i][t]);
                    ffma2(o2[i][0], aa, bp0);
                    ffma2(o2[i][1], aa, bp1);
                }
            }
        }
    }

    // Epilogue: ctx in (B, L, H*DK) layout
    #pragma unroll
    for (int i = 0; i < 8; i++) {
        const float inv_l = 1.0f / l_i[i];
        float o0, o1, o2v, o3;
        unpack2(o2[i][0], o0, o1);
        unpack2(o2[i][1], o2v, o3);
        *(float4*)&ctx[((size_t)(b*LL + q0 + row[i])) * DM + h*DKK + tx*4] =
            make_float4(o0*inv_l, o1*inv_l, o2v*inv_l, o3*inv_l);
    }
}

// ---------------------------------------------------------------------------
extern "C" void kernel_launch(void* const* d_in, const int* in_sizes, int n_in,
                              void* d_out, int out_size)
{
    const float* x    = (const float*)d_in[0];
    const float* Wq   = (const float*)d_in[1];
    const float* Wk   = (const float*)d_in[2];
    const float* Wv   = (const float*)d_in[3];
    const float* Wo   = (const float*)d_in[4];
    const float* bias = (const float*)d_in[5];
    const float* mask = (const float*)d_in[6];
    float* out = (float*)d_out;

    float *qp, *kp, *vp, *cp;
    cudaGetSymbolAddress((void**)&qp, g_q);
    cudaGetSymbolAddress((void**)&kp, g_k);
    cudaGetSymbolAddress((void**)&vp, g_v);
    cudaGetSymbolAddress((void**)&cp, g_ctx);

    const dim3 ggrid(DM / 128, MROWS / 128);   // (8, 32)
    gemm_nt_kernel<<<ggrid, 256>>>(x, Wq, qp, 1);
    gemm_nt_kernel<<<ggrid, 256>>>(x, Wk, kp, 1);
    gemm_nt_kernel<<<ggrid, 256>>>(x, Wv, vp, 1);

    const int smem_bytes = ATT_SMEM_FLOATS * (int)sizeof(float);  // 103424
    cudaFuncSetAttribute(attn_kernel,
                         cudaFuncAttributeMaxDynamicSharedMemorySize, smem_bytes);
    attn_kernel<<<dim3(LL / 128, BB * HH), 256, smem_bytes>>>(qp, kp, vp, bias, mask, cp);

    gemm_nt_kernel<<<ggrid, 256>>>(cp, Wo, out, 0);
}

// round 6
// speedup vs baseline: 2.6336x; 2.2063x over previous
#include <cuda_runtime.h>
#include <cuda_bf16.h>
#include <math.h>
#include <cstdint>

// Problem constants
#define BB   2
#define LL   2048
#define DM   1024
#define HH   16
#define DKK  64
#define MROWS (BB*LL)          // 4096
#define INV_SCALE 0.125f       // 1/sqrt(64)

typedef __nv_bfloat16 bf16;

// ---------------- scratch (__device__ globals, allocation-free) ----------------
__device__ bf16 g_xhi[(size_t)MROWS*DM];
__device__ bf16 g_xlo[(size_t)MROWS*DM];
__device__ bf16 g_wqhi[(size_t)DM*DM];
__device__ bf16 g_wqlo[(size_t)DM*DM];
__device__ bf16 g_wkhi[(size_t)DM*DM];
__device__ bf16 g_wklo[(size_t)DM*DM];
__device__ bf16 g_wvhi[(size_t)DM*DM];
__device__ bf16 g_wvlo[(size_t)DM*DM];
__device__ bf16 g_wohi[(size_t)DM*DM];
__device__ bf16 g_wolo[(size_t)DM*DM];
__device__ bf16 g_qhi[(size_t)BB*HH*LL*DKK];
__device__ bf16 g_qlo[(size_t)BB*HH*LL*DKK];
__device__ bf16 g_khi[(size_t)BB*HH*LL*DKK];
__device__ bf16 g_klo[(size_t)BB*HH*LL*DKK];
__device__ bf16 g_vhi[(size_t)BB*HH*LL*DKK];
__device__ bf16 g_vlo[(size_t)BB*HH*LL*DKK];
__device__ bf16 g_chi[(size_t)MROWS*DM];
__device__ bf16 g_clo[(size_t)MROWS*DM];

// ---------------- helpers ----------------
__device__ __forceinline__ uint32_t smem_u32(const void* p) {
    uint32_t a;
    asm("{ .reg .u64 t; cvta.to.shared.u64 t, %1; cvt.u32.u64 %0, t; }" : "=r"(a) : "l"(p));
    return a;
}
__device__ __forceinline__ void ldsm4(uint32_t* r, uint32_t a) {
    asm volatile("ldmatrix.sync.aligned.m8n8.x4.shared.b16 {%0,%1,%2,%3}, [%4];"
        : "=r"(r[0]), "=r"(r[1]), "=r"(r[2]), "=r"(r[3]) : "r"(a));
}
__device__ __forceinline__ void ldsm4t(uint32_t* r, uint32_t a) {
    asm volatile("ldmatrix.sync.aligned.m8n8.x4.trans.shared.b16 {%0,%1,%2,%3}, [%4];"
        : "=r"(r[0]), "=r"(r[1]), "=r"(r[2]), "=r"(r[3]) : "r"(a));
}
__device__ __forceinline__ void mma16816(float* c, const uint32_t* a, uint32_t b0, uint32_t b1) {
    asm volatile(
        "mma.sync.aligned.m16n8k16.row.col.f32.bf16.bf16.f32 "
        "{%0,%1,%2,%3}, {%4,%5,%6,%7}, {%8,%9}, {%0,%1,%2,%3};"
        : "+f"(c[0]), "+f"(c[1]), "+f"(c[2]), "+f"(c[3])
        : "r"(a[0]), "r"(a[1]), "r"(a[2]), "r"(a[3]), "r"(b0), "r"(b1));
}
__device__ __forceinline__ uint32_t pack_bf16x2(bf16 lo, bf16 hi) {
    __nv_bfloat162 t{lo, hi};
    return *reinterpret_cast<uint32_t*>(&t);
}
__device__ __forceinline__ void store_hilo(bf16* Hi, bf16* Lo, size_t idx, float x, float y) {
    bf16 hx = __float2bfloat16(x), hy = __float2bfloat16(y);
    __nv_bfloat162 hp{hx, hy};
    *reinterpret_cast<__nv_bfloat162*>(&Hi[idx]) = hp;
    __nv_bfloat162 lp{__float2bfloat16(x - __bfloat162float(hx)),
                      __float2bfloat16(y - __bfloat162float(hy))};
    *reinterpret_cast<__nv_bfloat162*>(&Lo[idx]) = lp;
}

extern __shared__ char dynsmem[];

// ---------------------------------------------------------------------------
// split: fp32 -> bf16 hi + bf16 lo
// ---------------------------------------------------------------------------
__global__ __launch_bounds__(256) void split_kernel(
    const float* __restrict__ in, bf16* __restrict__ hi, bf16* __restrict__ lo, int n4)
{
    int i = blockIdx.x * blockDim.x + threadIdx.x;
    if (i >= n4) return;
    float4 v = ((const float4*)in)[i];
    bf16 h0 = __float2bfloat16(v.x), h1 = __float2bfloat16(v.y);
    bf16 h2 = __float2bfloat16(v.z), h3 = __float2bfloat16(v.w);
    ((__nv_bfloat162*)hi)[2*i]   = {h0, h1};
    ((__nv_bfloat162*)hi)[2*i+1] = {h2, h3};
    ((__nv_bfloat162*)lo)[2*i]   = {__float2bfloat16(v.x - __bfloat162float(h0)),
                                    __float2bfloat16(v.y - __bfloat162float(h1))};
    ((__nv_bfloat162*)lo)[2*i+1] = {__float2bfloat16(v.z - __bfloat162float(h2)),
                                    __float2bfloat16(v.w - __bfloat162float(h3))};
}

// ---------------------------------------------------------------------------
// HMMA bf16-split NT GEMM: C[m][n] = sum_k A[m][k]*W[n][k]
// 3 products: Ahi*Whi + Ahi*Wlo + Alo*Whi, fp32 accum.
// Block 128x128, K-chunk 64, 8 warps (2M x 4N), warp tile 64x32.
// mode 0: fp32 row-major out; mode 1: bf16 hi/lo planes in head layout.
// ---------------------------------------------------------------------------
#define PAD 72                           // bf16 elems per smem row (144B stride)
#define GEMM_SMEM (4*128*PAD*2)          // 73728 bytes

__global__ __launch_bounds__(256, 2) void gemm_tc(
    const bf16* __restrict__ Ahi, const bf16* __restrict__ Alo,
    const bf16* __restrict__ Whi, const bf16* __restrict__ Wlo,
    float* __restrict__ Cf, bf16* __restrict__ Chi, bf16* __restrict__ Clo,
    int mode)
{
    bf16* sAh = (bf16*)dynsmem;
    bf16* sAl = sAh + 128*PAD;
    bf16* sWh = sAl + 128*PAD;
    bf16* sWl = sWh + 128*PAD;
    const uint32_t uAh = smem_u32(sAh), uAl = smem_u32(sAl);
    const uint32_t uWh = smem_u32(sWh), uWl = smem_u32(sWl);

    const int tid = threadIdx.x, lane = tid & 31, wid = tid >> 5;
    const int wm = wid >> 2, wn = wid & 3;
    const int m0 = blockIdx.y * 128, n0 = blockIdx.x * 128;
    const int r0 = lane >> 2, cq = (lane & 3) * 2;

    float acc[4][4][4];
    #pragma unroll
    for (int i = 0; i < 4; i++)
        #pragma unroll
        for (int j = 0; j < 4; j++)
            #pragma unroll
            for (int q = 0; q < 4; q++) acc[i][j][q] = 0.f;

    for (int kc = 0; kc < 16; kc++) {
        __syncthreads();
        #pragma unroll
        for (int it = 0; it < 4; it++) {
            const int idx = tid + it * 256;
            const int row = idx >> 3, c8 = idx & 7;
            const size_t ga = (size_t)(m0 + row) * DM + kc * 64 + c8 * 8;
            const size_t gw = (size_t)(n0 + row) * DM + kc * 64 + c8 * 8;
            *(uint4*)&sAh[row*PAD + c8*8] = *(const uint4*)&Ahi[ga];
            *(uint4*)&sAl[row*PAD + c8*8] = *(const uint4*)&Alo[ga];
            *(uint4*)&sWh[row*PAD + c8*8] = *(const uint4*)&Whi[gw];
            *(uint4*)&sWl[row*PAD + c8*8] = *(const uint4*)&Wlo[gw];
        }
        __syncthreads();

        #pragma unroll
        for (int t = 0; t < 4; t++) {
            const uint32_t qoff = (lane & 15) * (PAD*2) + t * 32 + (lane >> 4) * 16;
            uint32_t ah[4][4], al[4][4];
            #pragma unroll
            for (int mf = 0; mf < 4; mf++) {
                const uint32_t ra = (wm*64 + mf*16) * (PAD*2) + qoff;
                ldsm4(ah[mf], uAh + ra);
                ldsm4(al[mf], uAl + ra);
            }
            #pragma unroll
            for (int jp = 0; jp < 2; jp++) {
                const uint32_t rb = (wn*32 + jp*16) * (PAD*2) + qoff;
                uint32_t bh[4], bl[4];
                ldsm4(bh, uWh + rb);
                ldsm4(bl, uWl + rb);
                #pragma unroll
                for (int mf = 0; mf < 4; mf++) {
                    mma16816(acc[mf][2*jp],   ah[mf], bh[0], bh[2]);
                    mma16816(acc[mf][2*jp+1], ah[mf], bh[1], bh[3]);
                    mma16816(acc[mf][2*jp],   ah[mf], bl[0], bl[2]);
                    mma16816(acc[mf][2*jp+1], ah[mf], bl[1], bl[3]);
                    mma16816(acc[mf][2*jp],   al[mf], bh[0], bh[2]);
                    mma16816(acc[mf][2*jp+1], al[mf], bh[1], bh[3]);
                }
            }
        }
    }

    // epilogue
    #pragma unroll
    for (int mf = 0; mf < 4; mf++) {
        const int mr = m0 + wm*64 + mf*16 + r0;
        #pragma unroll
        for (int jf = 0; jf < 4; jf++) {
            const int col = n0 + wn*32 + jf*8 + cq;
            if (mode == 0) {
                *(float2*)&Cf[(size_t)mr * DM + col] =
                    make_float2(acc[mf][jf][0], acc[mf][jf][1]);
                *(float2*)&Cf[(size_t)(mr+8) * DM + col] =
                    make_float2(acc[mf][jf][2], acc[mf][jf][3]);
            } else {
                const int h = col >> 6, d = col & 63;
                const int b0_ = mr >> 11, l0 = mr & 2047;
                const size_t i0 = (((size_t)(b0_*HH + h) * LL + l0) * DKK + d);
                store_hilo(Chi, Clo, i0, acc[mf][jf][0], acc[mf][jf][1]);
                const int mr1 = mr + 8;
                const int b1_ = mr1 >> 11, l1 = mr1 & 2047;
                const size_t i1 = (((size_t)(b1_*HH + h) * LL + l1) * DKK + d);
                store_hilo(Chi, Clo, i1, acc[mf][jf][2], acc[mf][jf][3]);
            }
        }
    }
}

// ---------------------------------------------------------------------------
// HMMA flash attention, bf16-split, online softmax, bias + mask.
// Grid (L/128, B*H), 256 threads = 8 warps; warp = 16 q-rows x 64-key tile.
// ---------------------------------------------------------------------------
#define ATT_SMEM ((128*PAD*2 + 64*PAD*4) * 2)   // Qhi,Qlo 128 rows; K,V hi/lo 64 rows = 73728B

__global__ __launch_bounds__(256, 2) void attn_tc(
    const bf16* __restrict__ Qhi, const bf16* __restrict__ Qlo,
    const bf16* __restrict__ Khi, const bf16* __restrict__ Klo,
    const bf16* __restrict__ Vhi, const bf16* __restrict__ Vlo,
    const float* __restrict__ bias, const float* __restrict__ mask,
    bf16* __restrict__ Chi, bf16* __restrict__ Clo)
{
    bf16* sQh = (bf16*)dynsmem;
    bf16* sQl = sQh + 128*PAD;
    bf16* sKh = sQl + 128*PAD;
    bf16* sKl = sKh + 64*PAD;
    bf16* sVh = sKl + 64*PAD;
    bf16* sVl = sVh + 64*PAD;
    const uint32_t uQh = smem_u32(sQh), uQl = smem_u32(sQl);
    const uint32_t uKh = smem_u32(sKh), uKl = smem_u32(sKl);
    const uint32_t uVh = smem_u32(sVh), uVl = smem_u32(sVl);

    const int tid = threadIdx.x, lane = tid & 31, wid = tid >> 5;
    const int bh = blockIdx.y;
    const int b  = bh >> 4, h = bh & 15;
    const int q0 = blockIdx.x * 128;
    const int wr = wid * 16;
    const int r0 = lane >> 2, cq = (lane & 3) * 2;

    const bf16* Qhb = Qhi + (size_t)bh * LL * DKK;
    const bf16* Qlb = Qlo + (size_t)bh * LL * DKK;
    const bf16* Khb = Khi + (size_t)bh * LL * DKK;
    const bf16* Klb = Klo + (size_t)bh * LL * DKK;
    const bf16* Vhb = Vhi + (size_t)bh * LL * DKK;
    const bf16* Vlb = Vlo + (size_t)bh * LL * DKK;
    const float* brow0 = bias + ((size_t)bh * LL + (q0 + wr + r0)) * LL;
    const float* brow1 = brow0 + 8 * (size_t)LL;
    const float* maskb = mask + (size_t)b * LL;

    // load Q tile (128 rows x 64) hi/lo
    for (int i = tid; i < 128 * 8; i += 256) {
        const int row = i >> 3, c8 = i & 7;
        *(uint4*)&sQh[row*PAD + c8*8] = *(const uint4*)&Qhb[(size_t)(q0+row)*DKK + c8*8];
        *(uint4*)&sQl[row*PAD + c8*8] = *(const uint4*)&Qlb[(size_t)(q0+row)*DKK + c8*8];
    }

    float m_i[2] = {-1e30f, -1e30f}, l_i[2] = {0.f, 0.f};
    float oacc[8][4];
    #pragma unroll
    for (int j = 0; j < 8; j++)
        #pragma unroll
        for (int q = 0; q < 4; q++) oacc[j][q] = 0.f;

    for (int kt = 0; kt < LL/64; kt++) {
        const int k0 = kt * 64;
        __syncthreads();
        for (int i = tid; i < 64 * 8; i += 256) {
            const int row = i >> 3, c8 = i & 7;
            const size_t g = (size_t)(k0 + row) * DKK + c8 * 8;
            *(uint4*)&sKh[row*PAD + c8*8] = *(const uint4*)&Khb[g];
            *(uint4*)&sKl[row*PAD + c8*8] = *(const uint4*)&Klb[g];
            *(uint4*)&sVh[row*PAD + c8*8] = *(const uint4*)&Vhb[g];
            *(uint4*)&sVl[row*PAD + c8*8] = *(const uint4*)&Vlb[g];
        }
        __syncthreads();

        // ---- S = Q K^T ----
        float sacc[8][4];
        #pragma unroll
        for (int j = 0; j < 8; j++)
            #pragma unroll
            for (int q = 0; q < 4; q++) sacc[j][q] = 0.f;

        #pragma unroll
        for (int t = 0; t < 4; t++) {
            const uint32_t qoff = (lane & 15) * (PAD*2) + t * 32 + (lane >> 4) * 16;
            uint32_t qa[4], ql[4];
            ldsm4(qa, uQh + wr * (PAD*2) + qoff);
            ldsm4(ql, uQl + wr * (PAD*2) + qoff);
            #pragma unroll
            for (int jp = 0; jp < 4; jp++) {
                const uint32_t rb = (jp*16) * (PAD*2) + qoff;
                uint32_t kb[4], kl[4];
                ldsm4(kb, uKh + rb);
                ldsm4(kl, uKl + rb);
                mma16816(sacc[2*jp],   qa, kb[0], kb[2]);
                mma16816(sacc[2*jp+1], qa, kb[1], kb[3]);
                mma16816(sacc[2*jp],   qa, kl[0], kl[2]);
                mma16816(sacc[2*jp+1], qa, kl[1], kl[3]);
                mma16816(sacc[2*jp],   ql, kb[0], kb[2]);
                mma16816(sacc[2*jp+1], ql, kb[1], kb[3]);
            }
        }

        // ---- scale + bias + mask; row max ----
        float mx0 = -1e30f, mx1 = -1e30f;
        #pragma unroll
        for (int j = 0; j < 8; j++) {
            const int kc = k0 + j*8 + cq;
            float2 bz0 = *(const float2*)&brow0[kc];
            float2 bz1 = *(const float2*)&brow1[kc];
            float2 mz  = *(const float2*)&maskb[kc];
            sacc[j][0] = fmaf(sacc[j][0], INV_SCALE, bz0.x + mz.x);
            sacc[j][1] = fmaf(sacc[j][1], INV_SCALE, bz0.y + mz.y);
            sacc[j][2] = fmaf(sacc[j][2], INV_SCALE, bz1.x + mz.x);
            sacc[j][3] = fmaf(sacc[j][3], INV_SCALE, bz1.y + mz.y);
            mx0 = fmaxf(mx0, fmaxf(sacc[j][0], sacc[j][1]));
            mx1 = fmaxf(mx1, fmaxf(sacc[j][2], sacc[j][3]));
        }
        mx0 = fmaxf(mx0, __shfl_xor_sync(0xffffffffu, mx0, 1));
        mx0 = fmaxf(mx0, __shfl_xor_sync(0xffffffffu, mx0, 2));
        mx1 = fmaxf(mx1, __shfl_xor_sync(0xffffffffu, mx1, 1));
        mx1 = fmaxf(mx1, __shfl_xor_sync(0xffffffffu, mx1, 2));

        const float mn0 = fmaxf(m_i[0], mx0);
        const float mn1 = fmaxf(m_i[1], mx1);
        const float corr0 = __expf(m_i[0] - mn0);
        const float corr1 = __expf(m_i[1] - mn1);
        m_i[0] = mn0; m_i[1] = mn1;

        // ---- exp, split P into hi/lo frags ----
        uint32_t ph[4][4], pl[4][4];
        float rs0 = 0.f, rs1 = 0.f;
        #pragma unroll
        for (int j = 0; j < 8; j++) {
            float p0 = __expf(sacc[j][0] - mn0);
            float p1 = __expf(sacc[j][1] - mn0);
            float p2 = __expf(sacc[j][2] - mn1);
            float p3 = __expf(sacc[j][3] - mn1);
            rs0 += p0 + p1; rs1 += p2 + p3;
            bf16 h0 = __float2bfloat16(p0), h1 = __float2bfloat16(p1);
            bf16 h2 = __float2bfloat16(p2), h3 = __float2bfloat16(p3);
            const int t = j >> 1, s = (j & 1) * 2;
            ph[t][s+0] = pack_bf16x2(h0, h1);
            ph[t][s+1] = pack_bf16x2(h2, h3);
            pl[t][s+0] = pack_bf16x2(__float2bfloat16(p0 - __bfloat162float(h0)),
                                     __float2bfloat16(p1 - __bfloat162float(h1)));
            pl[t][s+1] = pack_bf16x2(__float2bfloat16(p2 - __bfloat162float(h2)),
                                     __float2bfloat16(p3 - __bfloat162float(h3)));
        }
        rs0 += __shfl_xor_sync(0xffffffffu, rs0, 1);
        rs0 += __shfl_xor_sync(0xffffffffu, rs0, 2);
        rs1 += __shfl_xor_sync(0xffffffffu, rs1, 1);
        rs1 += __shfl_xor_sync(0xffffffffu, rs1, 2);
        l_i[0] = l_i[0] * corr0 + rs0;
        l_i[1] = l_i[1] * corr1 + rs1;

        #pragma unroll
        for (int j = 0; j < 8; j++) {
            oacc[j][0] *= corr0; oacc[j][1] *= corr0;
            oacc[j][2] *= corr1; oacc[j][3] *= corr1;
        }

        // ---- O += P V ----
        #pragma unroll
        for (int j = 0; j < 8; j++) {
            #pragma unroll
            for (int tp = 0; tp < 2; tp++) {
                const uint32_t va = (tp*32 + lane) * (PAD*2) + j * 16;
                uint32_t vh[4], vl[4];
                ldsm4t(vh, uVh + va);
                ldsm4t(vl, uVl + va);
                mma16816(oacc[j], ph[2*tp],   vh[0], vh[1]);
                mma16816(oacc[j], ph[2*tp],   vl[0], vl[1]);
                mma16816(oacc[j], pl[2*tp],   vh[0], vh[1]);
                mma16816(oacc[j], ph[2*tp+1], vh[2], vh[3]);
                mma16816(oacc[j], ph[2*tp+1], vl[2], vl[3]);
                mma16816(oacc[j], pl[2*tp+1], vh[2], vh[3]);
            }
        }
    }

    // ---- epilogue: write ctx hi/lo bf16 planes, (B*L, DM) layout ----
    const float inv0 = 1.0f / l_i[0];
    const float inv1 = 1.0f / l_i[1];
    const size_t row0 = (size_t)(b * LL + q0 + wr + r0);
    const size_t row1 = row0 + 8;
    #pragma unroll
    for (int j = 0; j < 8; j++) {
        const int col = h * DKK + j * 8 + cq;
        store_hilo(Chi, Clo, row0 * DM + col, oacc[j][0] * inv0, oacc[j][1] * inv0);
        store_hilo(Chi, Clo, row1 * DM + col, oacc[j][2] * inv1, oacc[j][3] * inv1);
    }
}

// ---------------------------------------------------------------------------
extern "C" void kernel_launch(void* const* d_in, const int* in_sizes, int n_in,
                              void* d_out, int out_size)
{
    const float* x    = (const float*)d_in[0];
    const float* Wq   = (const float*)d_in[1];
    const float* Wk   = (const float*)d_in[2];
    const float* Wv   = (const float*)d_in[3];
    const float* Wo   = (const float*)d_in[4];
    const float* bias = (const float*)d_in[5];
    const float* mask = (const float*)d_in[6];
    float* out = (float*)d_out;

    bf16 *xhi, *xlo, *wqhi, *wqlo, *wkhi, *wklo, *wvhi, *wvlo, *wohi, *wolo;
    bf16 *qhi, *qlo, *khi, *klo, *vhi, *vlo, *chi, *clo;
    cudaGetSymbolAddress((void**)&xhi, g_xhi);   cudaGetSymbolAddress((void**)&xlo, g_xlo);
    cudaGetSymbolAddress((void**)&wqhi, g_wqhi); cudaGetSymbolAddress((void**)&wqlo, g_wqlo);
    cudaGetSymbolAddress((void**)&wkhi, g_wkhi); cudaGetSymbolAddress((void**)&wklo, g_wklo);
    cudaGetSymbolAddress((void**)&wvhi, g_wvhi); cudaGetSymbolAddress((void**)&wvlo, g_wvlo);
    cudaGetSymbolAddress((void**)&wohi, g_wohi); cudaGetSymbolAddress((void**)&wolo, g_wolo);
    cudaGetSymbolAddress((void**)&qhi, g_qhi);   cudaGetSymbolAddress((void**)&qlo, g_qlo);
    cudaGetSymbolAddress((void**)&khi, g_khi);   cudaGetSymbolAddress((void**)&klo, g_klo);
    cudaGetSymbolAddress((void**)&vhi, g_vhi);   cudaGetSymbolAddress((void**)&vlo, g_vlo);
    cudaGetSymbolAddress((void**)&chi, g_chi);   cudaGetSymbolAddress((void**)&clo, g_clo);

    const int nx4 = MROWS * DM / 4;
    const int nw4 = DM * DM / 4;
    split_kernel<<<(nx4 + 255) / 256, 256>>>(x,  xhi,  xlo,  nx4);
    split_kernel<<<(nw4 + 255) / 256, 256>>>(Wq, wqhi, wqlo, nw4);
    split_kernel<<<(nw4 + 255) / 256, 256>>>(Wk, wkhi, wklo, nw4);
    split_kernel<<<(nw4 + 255) / 256, 256>>>(Wv, wvhi, wvlo, nw4);
    split_kernel<<<(nw4 + 255) / 256, 256>>>(Wo, wohi, wolo, nw4);

    cudaFuncSetAttribute(gemm_tc, cudaFuncAttributeMaxDynamicSharedMemorySize, GEMM_SMEM);
    cudaFuncSetAttribute(attn_tc, cudaFuncAttributeMaxDynamicSharedMemorySize, ATT_SMEM);

    const dim3 ggrid(DM / 128, MROWS / 128);   // (8, 32)
    gemm_tc<<<ggrid, 256, GEMM_SMEM>>>(xhi, xlo, wqhi, wqlo, nullptr, qhi, qlo, 1);
    gemm_tc<<<ggrid, 256, GEMM_SMEM>>>(xhi, xlo, wkhi, wklo, nullptr, khi, klo, 1);
    gemm_tc<<<ggrid, 256, GEMM_SMEM>>>(xhi, xlo, wvhi, wvlo, nullptr, vhi, vlo, 1);

    attn_tc<<<dim3(LL / 128, BB * HH), 256, ATT_SMEM>>>(
        qhi, qlo, khi, klo, vhi, vlo, bias, mask, chi, clo);

    gemm_tc<<<ggrid, 256, GEMM_SMEM>>>(chi, clo, wohi, wolo, out, nullptr, nullptr, 0);
}